// round 15
// baseline (speedup 1.0000x reference)
#include <cuda_runtime.h>
#include <cuda_bf16.h>
#include <cstdint>

// Problem constants
#define Bsz 4
#define Cch 512
#define Np  4096     // H*W = 64*64
#define Cqd 64

// Scratch (device globals; allocation-free per harness rules)
__device__ float g_q[Bsz * Np * Cqd];                       // [B][N][Cq]   4 MB
__device__ float g_k[Bsz * Np * Cqd];                       // [B][N][Cq]   4 MB
__device__ float g_rowsum[Bsz * Np];                        // exp row sums 64 KB
__device__ __nv_bfloat16 g_pb[(size_t)Bsz * Np * Np];       // exp(sim) bf16 128 MB
__device__ __nv_bfloat16 g_vt[(size_t)Bsz * Cch * Np];      // V^T bf16    16 MB

#define EXP_OFF 32.0f   // fixed logit shift: neutral in softmax ratio, overflow guard

// ---------------------------------------------------------------------------
// Helpers
// ---------------------------------------------------------------------------
__device__ __forceinline__ unsigned f2tf32(float f) {
    unsigned u;
    asm("cvt.rna.tf32.f32 %0, %1;" : "=r"(u) : "f"(f));
    return u;
}

__device__ __forceinline__ void mma_tf32(float* d, const unsigned* a, const unsigned* b) {
    asm volatile(
        "mma.sync.aligned.m16n8k8.row.col.f32.tf32.tf32.f32 "
        "{%0,%1,%2,%3}, {%4,%5,%6,%7}, {%8,%9}, {%0,%1,%2,%3};\n"
        : "+f"(d[0]), "+f"(d[1]), "+f"(d[2]), "+f"(d[3])
        : "r"(a[0]), "r"(a[1]), "r"(a[2]), "r"(a[3]), "r"(b[0]), "r"(b[1]));
}

__device__ __forceinline__ void mma_bf16(float* d, const unsigned* a, const unsigned* b) {
    asm volatile(
        "mma.sync.aligned.m16n8k16.row.col.f32.bf16.bf16.f32 "
        "{%0,%1,%2,%3}, {%4,%5,%6,%7}, {%8,%9}, {%0,%1,%2,%3};\n"
        : "+f"(d[0]), "+f"(d[1]), "+f"(d[2]), "+f"(d[3])
        : "r"(a[0]), "r"(a[1]), "r"(a[2]), "r"(a[3]), "r"(b[0]), "r"(b[1]));
}

__device__ __forceinline__ uint32_t pack2(__nv_bfloat16 a, __nv_bfloat16 b) {
    __nv_bfloat162 v = __halves2bfloat162(a, b);
    return *reinterpret_cast<uint32_t*>(&v);
}

__device__ __forceinline__ void split_bf16(float v, __nv_bfloat16& h, __nv_bfloat16& l) {
    h = __float2bfloat16_rn(v);
    l = __float2bfloat16_rn(v - __bfloat162float(h));
}

// ---------------------------------------------------------------------------
// Zero the rowsum accumulator (kernel-launch-only graph; no memset nodes).
// ---------------------------------------------------------------------------
__global__ void zero_rowsum_kernel(float* __restrict__ rs) {
    rs[blockIdx.x * 256 + threadIdx.x] = 0.0f;
}

// ---------------------------------------------------------------------------
// fp32 projection (Q and K only; tiny: Cq=64)
// out[b][n][o] = sum_c W[o][c] * x[b][c][n] + bias[o]
// ---------------------------------------------------------------------------
__global__ void proj_kernel(const float* __restrict__ x,
                            const float* __restrict__ W,
                            const float* __restrict__ bias,
                            float* __restrict__ out, int Co) {
    const int n0 = blockIdx.x * 128;
    const int o0 = blockIdx.y * 64;
    const int b  = blockIdx.z;
    __shared__ float xs[32][128];
    __shared__ float ws[64][33];
    const int t  = threadIdx.x;
    const int ox = t & 15;
    const int ny = t >> 4;
    float acc[8][4] = {};
    const float* xb = x + (size_t)b * Cch * Np;

    for (int c0 = 0; c0 < Cch; c0 += 32) {
        #pragma unroll
        for (int r = 0; r < 16; r++) {
            int l = t + 256 * r;
            int cc = l >> 7, nn = l & 127;
            xs[cc][nn] = xb[(size_t)(c0 + cc) * Np + n0 + nn];
        }
        #pragma unroll
        for (int r = 0; r < 8; r++) {
            int l = t + 256 * r;
            int oo = l >> 5, cc = l & 31;
            ws[oo][cc] = W[(o0 + oo) * Cch + c0 + cc];
        }
        __syncthreads();
        #pragma unroll
        for (int cc = 0; cc < 32; cc++) {
            float a[8], bb[4];
            #pragma unroll
            for (int i = 0; i < 8; i++) a[i] = xs[cc][ny + 16 * i];
            #pragma unroll
            for (int j = 0; j < 4; j++) bb[j] = ws[ox + 16 * j][cc];
            #pragma unroll
            for (int i = 0; i < 8; i++)
                #pragma unroll
                for (int j = 0; j < 4; j++) acc[i][j] += a[i] * bb[j];
        }
        __syncthreads();
    }
    #pragma unroll
    for (int j = 0; j < 4; j++) {
        float bv = bias[o0 + ox + 16 * j];
        #pragma unroll
        for (int i = 0; i < 8; i++) {
            int n = n0 + ny + 16 * i;
            out[((size_t)b * Np + n) * Co + o0 + ox + 16 * j] = acc[i][j] + bv;
        }
    }
}

// ---------------------------------------------------------------------------
// V projection via tf32 MMA. Emits V^T bf16: vt[b][c][m].
//   v[c][m] = sum_k Wv[c][k] * x[b][k][m] + bv[c]
// ---------------------------------------------------------------------------
#define WS_STRIDE 36
#define XS_STRIDE 136
#define WS_BUF (128 * WS_STRIDE)
#define XS_BUF (32 * XS_STRIDE)
#define VP_SMEM ((2 * WS_BUF + 2 * XS_BUF) * 4)   // 71680 bytes

__global__ __launch_bounds__(256, 2) void vproj_tc_kernel(
        const float* __restrict__ x,
        const float* __restrict__ W,
        const float* __restrict__ bias,
        __nv_bfloat16* __restrict__ vt) {
    const int nB = blockIdx.x * 128;
    const int cB = blockIdx.y * 128;
    const int b  = blockIdx.z;

    extern __shared__ unsigned sm[];
    unsigned* Ws = sm;
    unsigned* Xs = sm + 2 * WS_BUF;

    const int t    = threadIdx.x;
    const int wid  = t >> 5;
    const int lane = t & 31;
    const int gid  = lane >> 2;
    const int tig  = lane & 3;
    const int wc   = (wid >> 2) * 64;
    const int wn   = (wid & 3) * 32;

    const float* xb = x + (size_t)b * Cch * Np;

    float acc[4][4][4] = {};
    float4 wst[4], xst[4];

    #pragma unroll
    for (int r = 0; r < 4; r++) {
        int l4 = t + 256 * r;
        wst[r] = *(const float4*)(W + (size_t)(cB + (l4 >> 3)) * Cch + (l4 & 7) * 4);
        xst[r] = *(const float4*)(xb + (size_t)(l4 >> 5) * Np + nB + (l4 & 31) * 4);
    }
    #pragma unroll
    for (int r = 0; r < 4; r++) {
        int l4 = t + 256 * r;
        unsigned* wd = Ws + (l4 >> 3) * WS_STRIDE + (l4 & 7) * 4;
        wd[0] = f2tf32(wst[r].x); wd[1] = f2tf32(wst[r].y);
        wd[2] = f2tf32(wst[r].z); wd[3] = f2tf32(wst[r].w);
        unsigned* xd = Xs + (l4 >> 5) * XS_STRIDE + (l4 & 31) * 4;
        xd[0] = f2tf32(xst[r].x); xd[1] = f2tf32(xst[r].y);
        xd[2] = f2tf32(xst[r].z); xd[3] = f2tf32(xst[r].w);
    }
    __syncthreads();

    const int NI = Cch / 32;
    for (int it = 0; it < NI; it++) {
        const int cur = it & 1;
        if (it + 1 < NI) {
            const int c0 = (it + 1) * 32;
            #pragma unroll
            for (int r = 0; r < 4; r++) {
                int l4 = t + 256 * r;
                wst[r] = *(const float4*)(W + (size_t)(cB + (l4 >> 3)) * Cch + c0 + (l4 & 7) * 4);
                xst[r] = *(const float4*)(xb + (size_t)(c0 + (l4 >> 5)) * Np + nB + (l4 & 31) * 4);
            }
        }
        const unsigned* Wc = Ws + cur * WS_BUF;
        const unsigned* Xc = Xs + cur * XS_BUF;
        #pragma unroll
        for (int ks = 0; ks < 4; ks++) {
            const int kb = ks * 8;
            unsigned afr[4][4];
            #pragma unroll
            for (int mt = 0; mt < 4; mt++) {
                int row = wc + mt * 16 + gid;
                afr[mt][0] = Wc[row * WS_STRIDE + kb + tig];
                afr[mt][1] = Wc[(row + 8) * WS_STRIDE + kb + tig];
                afr[mt][2] = Wc[row * WS_STRIDE + kb + tig + 4];
                afr[mt][3] = Wc[(row + 8) * WS_STRIDE + kb + tig + 4];
            }
            unsigned bfr[4][2];
            #pragma unroll
            for (int nt = 0; nt < 4; nt++) {
                int col = wn + nt * 8 + gid;
                bfr[nt][0] = Xc[(kb + tig) * XS_STRIDE + col];
                bfr[nt][1] = Xc[(kb + tig + 4) * XS_STRIDE + col];
            }
            #pragma unroll
            for (int mt = 0; mt < 4; mt++)
                #pragma unroll
                for (int nt = 0; nt < 4; nt++)
                    mma_tf32(acc[mt][nt], afr[mt], bfr[nt]);
        }
        if (it + 1 < NI) {
            unsigned* Wd = Ws + (cur ^ 1) * WS_BUF;
            unsigned* Xd = Xs + (cur ^ 1) * XS_BUF;
            #pragma unroll
            for (int r = 0; r < 4; r++) {
                int l4 = t + 256 * r;
                unsigned* wd = Wd + (l4 >> 3) * WS_STRIDE + (l4 & 7) * 4;
                wd[0] = f2tf32(wst[r].x); wd[1] = f2tf32(wst[r].y);
                wd[2] = f2tf32(wst[r].z); wd[3] = f2tf32(wst[r].w);
                unsigned* xd = Xd + (l4 >> 5) * XS_STRIDE + (l4 & 31) * 4;
                xd[0] = f2tf32(xst[r].x); xd[1] = f2tf32(xst[r].y);
                xd[2] = f2tf32(xst[r].z); xd[3] = f2tf32(xst[r].w);
            }
            __syncthreads();
        }
    }

    // Epilogue: round to bf16, store V^T [c][m=n]
    __nv_bfloat16* Vb = vt + (size_t)b * Cch * Np;
    #pragma unroll
    for (int mt = 0; mt < 4; mt++) {
        int c = cB + wc + mt * 16 + gid;
        float b0 = bias[c], b1 = bias[c + 8];
        #pragma unroll
        for (int nt = 0; nt < 4; nt++) {
            int n = nB + wn + nt * 8 + 2 * tig;
            *(uint32_t*)(Vb + (size_t)c * Np + n) =
                pack2(__float2bfloat16_rn(acc[mt][nt][0] + b0),
                      __float2bfloat16_rn(acc[mt][nt][1] + b0));
            *(uint32_t*)(Vb + (size_t)(c + 8) * Np + n) =
                pack2(__float2bfloat16_rn(acc[mt][nt][2] + b1),
                      __float2bfloat16_rn(acc[mt][nt][3] + b1));
        }
    }
}

// ---------------------------------------------------------------------------
// sim via 3x bf16 split MMA (hh + hl + lh), FUSED exp epilogue:
//   e[n][m] = exp(q.k - EXP_OFF)  -> bf16 P;  rowsum[n] += partial sums.
// launch_bounds(256,2): sim compiles at 128 regs already -> 2 CTAs/SM free.
// ---------------------------------------------------------------------------
#define QB_STRIDE 20
#define QB_BUF (128 * QB_STRIDE)     // 2560 words = 10240 B per plane

__global__ __launch_bounds__(256, 2) void sim_bf16_kernel(
        const float* __restrict__ q,
        const float* __restrict__ k,
        __nv_bfloat16* __restrict__ P,
        float* __restrict__ rowsum) {
    const int m0 = blockIdx.x * 128;
    const int n0 = blockIdx.y * 128;
    const int b  = blockIdx.z;

    __shared__ uint32_t qh[QB_BUF], ql[QB_BUF], kh[QB_BUF], kl[QB_BUF];

    const int t    = threadIdx.x;
    const int wid  = t >> 5;
    const int lane = t & 31;
    const int gid  = lane >> 2;
    const int tig  = lane & 3;
    const int wn   = (wid >> 2) * 64;
    const int wm   = (wid & 3) * 32;

    const float* qb = q + ((size_t)b * Np + n0) * Cqd;
    const float* kb = k + ((size_t)b * Np + m0) * Cqd;

    float acc[4][4][4] = {};

    for (int c0 = 0; c0 < Cqd; c0 += 32) {
        if (c0) __syncthreads();
        #pragma unroll
        for (int r = 0; r < 4; r++) {
            int l4 = t + 256 * r;
            int row = l4 >> 3, j4 = (l4 & 7) * 4;
            float4 vq = *(const float4*)(qb + row * Cqd + c0 + j4);
            float4 vk = *(const float4*)(kb + row * Cqd + c0 + j4);
            __nv_bfloat16 hx, lx, hy, ly, hz, lz, hw, lw;
            int w0 = row * QB_STRIDE + (j4 >> 1);
            split_bf16(vq.x, hx, lx); split_bf16(vq.y, hy, ly);
            split_bf16(vq.z, hz, lz); split_bf16(vq.w, hw, lw);
            qh[w0]     = pack2(hx, hy); qh[w0 + 1] = pack2(hz, hw);
            ql[w0]     = pack2(lx, ly); ql[w0 + 1] = pack2(lz, lw);
            split_bf16(vk.x, hx, lx); split_bf16(vk.y, hy, ly);
            split_bf16(vk.z, hz, lz); split_bf16(vk.w, hw, lw);
            kh[w0]     = pack2(hx, hy); kh[w0 + 1] = pack2(hz, hw);
            kl[w0]     = pack2(lx, ly); kl[w0 + 1] = pack2(lz, lw);
        }
        __syncthreads();

        #pragma unroll
        for (int ks = 0; ks < 2; ks++) {
            const int kb8 = ks * 8;
            unsigned ah[4][4], al[4][4];
            #pragma unroll
            for (int mt = 0; mt < 4; mt++) {
                int row = wn + mt * 16 + gid;
                ah[mt][0] = qh[row * QB_STRIDE + kb8 + tig];
                ah[mt][1] = qh[(row + 8) * QB_STRIDE + kb8 + tig];
                ah[mt][2] = qh[row * QB_STRIDE + kb8 + tig + 4];
                ah[mt][3] = qh[(row + 8) * QB_STRIDE + kb8 + tig + 4];
                al[mt][0] = ql[row * QB_STRIDE + kb8 + tig];
                al[mt][1] = ql[(row + 8) * QB_STRIDE + kb8 + tig];
                al[mt][2] = ql[row * QB_STRIDE + kb8 + tig + 4];
                al[mt][3] = ql[(row + 8) * QB_STRIDE + kb8 + tig + 4];
            }
            unsigned bh[4][2], bl[4][2];
            #pragma unroll
            for (int nt = 0; nt < 4; nt++) {
                int col = wm + nt * 8 + gid;
                bh[nt][0] = kh[col * QB_STRIDE + kb8 + tig];
                bh[nt][1] = kh[col * QB_STRIDE + kb8 + tig + 4];
                bl[nt][0] = kl[col * QB_STRIDE + kb8 + tig];
                bl[nt][1] = kl[col * QB_STRIDE + kb8 + tig + 4];
            }
            #pragma unroll
            for (int mt = 0; mt < 4; mt++)
                #pragma unroll
                for (int nt = 0; nt < 4; nt++) {
                    mma_bf16(acc[mt][nt], ah[mt], bl[nt]);
                    mma_bf16(acc[mt][nt], al[mt], bh[nt]);
                    mma_bf16(acc[mt][nt], ah[mt], bh[nt]);
                }
        }
    }

    // Fused exp epilogue
    #pragma unroll
    for (int mt = 0; mt < 4; mt++)
        #pragma unroll
        for (int nt = 0; nt < 4; nt++)
            #pragma unroll
            for (int v = 0; v < 4; v++)
                acc[mt][nt][v] = __expf(acc[mt][nt][v] - EXP_OFF);

    __nv_bfloat16* Pb = P + ((size_t)b * Np + n0) * Np + m0;
    #pragma unroll
    for (int mt = 0; mt < 4; mt++) {
        int n = wn + mt * 16 + gid;
        #pragma unroll
        for (int nt = 0; nt < 4; nt++) {
            int m = wm + nt * 8 + 2 * tig;
            *(uint32_t*)(Pb + (size_t)n * Np + m) =
                pack2(__float2bfloat16_rn(acc[mt][nt][0]),
                      __float2bfloat16_rn(acc[mt][nt][1]));
            *(uint32_t*)(Pb + (size_t)(n + 8) * Np + m) =
                pack2(__float2bfloat16_rn(acc[mt][nt][2]),
                      __float2bfloat16_rn(acc[mt][nt][3]));
        }
    }

    float* rs = rowsum + (size_t)b * Np + n0;
    #pragma unroll
    for (int mt = 0; mt < 4; mt++) {
        float s0 = 0.f, s1 = 0.f;
        #pragma unroll
        for (int nt = 0; nt < 4; nt++) {
            s0 += acc[mt][nt][0] + acc[mt][nt][1];
            s1 += acc[mt][nt][2] + acc[mt][nt][3];
        }
        s0 += __shfl_xor_sync(0xFFFFFFFF, s0, 1);
        s0 += __shfl_xor_sync(0xFFFFFFFF, s0, 2);
        s1 += __shfl_xor_sync(0xFFFFFFFF, s1, 1);
        s1 += __shfl_xor_sync(0xFFFFFFFF, s1, 2);
        if (tig == 0) {
            int n = wn + mt * 16 + gid;
            atomicAdd(rs + n, s0);
            atomicAdd(rs + n + 8, s1);
        }
    }
}

// ---------------------------------------------------------------------------
// ctx via bf16 mma.sync m16n8k16, 128x128 tile (round-13 config),
// launch_bounds(256,2) for 2 CTAs/SM; epilogue divides by rowsum:
//   out[b][c][n] = g * (sum_m e[n][m]*V[m][c]) / rowsum[n] + x
// ---------------------------------------------------------------------------
#define PS2 20
#define CT_BUF (128 * PS2)

__global__ __launch_bounds__(256, 2) void ctx_bf16_kernel(
        const __nv_bfloat16* __restrict__ P,
        const __nv_bfloat16* __restrict__ Vt,
        const float* __restrict__ rowsum,
        const float* __restrict__ x,
        const float* __restrict__ gamma,
        float* __restrict__ out) {
    const int n0 = blockIdx.x * 128;
    const int c0 = blockIdx.y * 128;
    const int b  = blockIdx.z;

    __shared__ uint32_t Ps[2][CT_BUF];
    __shared__ uint32_t Vs[2][CT_BUF];

    const int t    = threadIdx.x;
    const int wid  = t >> 5;
    const int lane = t & 31;
    const int gid  = lane >> 2;
    const int tig  = lane & 3;
    const int wn   = (wid >> 2) * 64;
    const int wc   = (wid & 3) * 32;

    const __nv_bfloat16* Pb = P + ((size_t)b * Np + n0) * Np;
    const __nv_bfloat16* Vb = Vt + ((size_t)b * Cch + c0) * Np;

    float acc[4][4][4] = {};
    uint4 pst[2], vst[2];

    #pragma unroll
    for (int r = 0; r < 2; r++) {
        int l = t + 256 * r;
        int row = l >> 2, u = l & 3;
        pst[r] = *(const uint4*)(Pb + (size_t)row * Np + u * 8);
        vst[r] = *(const uint4*)(Vb + (size_t)row * Np + u * 8);
    }
    #pragma unroll
    for (int r = 0; r < 2; r++) {
        int l = t + 256 * r;
        int row = l >> 2, u = l & 3;
        uint32_t* pd = &Ps[0][row * PS2 + u * 4];
        pd[0] = pst[r].x; pd[1] = pst[r].y; pd[2] = pst[r].z; pd[3] = pst[r].w;
        uint32_t* vd = &Vs[0][row * PS2 + u * 4];
        vd[0] = vst[r].x; vd[1] = vst[r].y; vd[2] = vst[r].z; vd[3] = vst[r].w;
    }
    __syncthreads();

    const int NI = Np / 32;
    for (int it = 0; it < NI; it++) {
        const int cur = it & 1;
        if (it + 1 < NI) {
            const __nv_bfloat16* Pn = Pb + (it + 1) * 32;
            const __nv_bfloat16* Vn = Vb + (it + 1) * 32;
            #pragma unroll
            for (int r = 0; r < 2; r++) {
                int l = t + 256 * r;
                int row = l >> 2, u = l & 3;
                pst[r] = *(const uint4*)(Pn + (size_t)row * Np + u * 8);
                vst[r] = *(const uint4*)(Vn + (size_t)row * Np + u * 8);
            }
        }
        const uint32_t* Pc = Ps[cur];
        const uint32_t* Vc = Vs[cur];
        #pragma unroll
        for (int ks = 0; ks < 2; ks++) {
            const int kb = ks * 8;
            unsigned afr[4][4];
            #pragma unroll
            for (int mt = 0; mt < 4; mt++) {
                int row = wn + mt * 16 + gid;
                afr[mt][0] = Pc[row * PS2 + kb + tig];
                afr[mt][1] = Pc[(row + 8) * PS2 + kb + tig];
                afr[mt][2] = Pc[row * PS2 + kb + tig + 4];
                afr[mt][3] = Pc[(row + 8) * PS2 + kb + tig + 4];
            }
            unsigned bfr[4][2];
            #pragma unroll
            for (int nt = 0; nt < 4; nt++) {
                int col = wc + nt * 8 + gid;
                bfr[nt][0] = Vc[col * PS2 + kb + tig];
                bfr[nt][1] = Vc[col * PS2 + kb + tig + 4];
            }
            #pragma unroll
            for (int mt = 0; mt < 4; mt++)
                #pragma unroll
                for (int nt = 0; nt < 4; nt++)
                    mma_bf16(acc[mt][nt], afr[mt], bfr[nt]);
        }
        if (it + 1 < NI) {
            uint32_t* Pd = Ps[cur ^ 1];
            uint32_t* Vd = Vs[cur ^ 1];
            #pragma unroll
            for (int r = 0; r < 2; r++) {
                int l = t + 256 * r;
                int row = l >> 2, u = l & 3;
                uint32_t* pd = &Pd[row * PS2 + u * 4];
                pd[0] = pst[r].x; pd[1] = pst[r].y; pd[2] = pst[r].z; pd[3] = pst[r].w;
                uint32_t* vd = &Vd[row * PS2 + u * 4];
                vd[0] = vst[r].x; vd[1] = vst[r].y; vd[2] = vst[r].z; vd[3] = vst[r].w;
            }
            __syncthreads();
        }
    }

    // Epilogue: out[b][c][n] = g * acc / rowsum[n] + x
    const float g = gamma[0];
    const float* rs = rowsum + (size_t)b * Np + n0;
    #pragma unroll
    for (int mt = 0; mt < 4; mt++) {
        int n = n0 + wn + mt * 16 + gid;
        float inv0 = g / rs[wn + mt * 16 + gid];
        float inv1 = g / rs[wn + mt * 16 + gid + 8];
        #pragma unroll
        for (int nt = 0; nt < 4; nt++) {
            int c = c0 + wc + nt * 8 + 2 * tig;
            size_t i00 = ((size_t)b * Cch + c) * Np + n;
            size_t i01 = ((size_t)b * Cch + c + 1) * Np + n;
            out[i00]     = inv0 * acc[mt][nt][0] + x[i00];
            out[i01]     = inv0 * acc[mt][nt][1] + x[i01];
            out[i00 + 8] = inv1 * acc[mt][nt][2] + x[i00 + 8];
            out[i01 + 8] = inv1 * acc[mt][nt][3] + x[i01 + 8];
        }
    }
}

// ---------------------------------------------------------------------------
extern "C" void kernel_launch(void* const* d_in, const int* in_sizes, int n_in,
                              void* d_out, int out_size) {
    const float* x     = (const float*)d_in[0];
    const float* Wq    = (const float*)d_in[1];
    const float* bq    = (const float*)d_in[2];
    const float* Wk    = (const float*)d_in[3];
    const float* bk    = (const float*)d_in[4];
    const float* Wv    = (const float*)d_in[5];
    const float* bv    = (const float*)d_in[6];
    const float* gamma = (const float*)d_in[7];
    float* out = (float*)d_out;

    float *q, *k, *rsum;
    __nv_bfloat16 *pb, *vt;
    cudaGetSymbolAddress((void**)&q, g_q);
    cudaGetSymbolAddress((void**)&k, g_k);
    cudaGetSymbolAddress((void**)&rsum, g_rowsum);
    cudaGetSymbolAddress((void**)&pb, g_pb);
    cudaGetSymbolAddress((void**)&vt, g_vt);

    static int smem_set = 0;
    if (!smem_set) {
        cudaFuncSetAttribute(vproj_tc_kernel,
                             cudaFuncAttributeMaxDynamicSharedMemorySize, VP_SMEM);
        smem_set = 1;
    }

    dim3 thr(256);
    zero_rowsum_kernel<<<Bsz * Np / 256, thr>>>(rsum);
    proj_kernel<<<dim3(Np / 128, 1, Bsz), thr>>>(x, Wq, bq, q, Cqd);
    proj_kernel<<<dim3(Np / 128, 1, Bsz), thr>>>(x, Wk, bk, k, Cqd);
    vproj_tc_kernel<<<dim3(Np / 128, Cch / 128, Bsz), thr, VP_SMEM>>>(x, Wv, bv, vt);
    sim_bf16_kernel<<<dim3(Np / 128, Np / 128, Bsz), thr>>>(q, k, pb, rsum);
    ctx_bf16_kernel<<<dim3(Np / 128, Cch / 128, Bsz), thr>>>(pb, vt, rsum, x, gamma, out);
}

// round 17
// speedup vs baseline: 1.0268x; 1.0268x over previous
#include <cuda_runtime.h>
#include <cuda_bf16.h>
#include <cstdint>

// Problem constants
#define Bsz 4
#define Cch 512
#define Np  4096     // H*W = 64*64
#define Cqd 64

// Scratch (device globals; allocation-free per harness rules)
__device__ float g_q[Bsz * Np * Cqd];                       // [B][N][Cq]   4 MB
__device__ float g_k[Bsz * Np * Cqd];                       // [B][N][Cq]   4 MB
__device__ float g_rowsum[Bsz * Np];                        // exp row sums 64 KB
__device__ __nv_bfloat16 g_pb[(size_t)Bsz * Np * Np];       // exp(sim) bf16 128 MB
__device__ __nv_bfloat16 g_vt[(size_t)Bsz * Cch * Np];      // V^T bf16    16 MB

#define EXP_OFF 32.0f   // fixed logit shift: neutral in softmax ratio, overflow guard

// ---------------------------------------------------------------------------
// Helpers
// ---------------------------------------------------------------------------
__device__ __forceinline__ unsigned f2tf32(float f) {
    unsigned u;
    asm("cvt.rna.tf32.f32 %0, %1;" : "=r"(u) : "f"(f));
    return u;
}

__device__ __forceinline__ void mma_tf32(float* d, const unsigned* a, const unsigned* b) {
    asm volatile(
        "mma.sync.aligned.m16n8k8.row.col.f32.tf32.tf32.f32 "
        "{%0,%1,%2,%3}, {%4,%5,%6,%7}, {%8,%9}, {%0,%1,%2,%3};\n"
        : "+f"(d[0]), "+f"(d[1]), "+f"(d[2]), "+f"(d[3])
        : "r"(a[0]), "r"(a[1]), "r"(a[2]), "r"(a[3]), "r"(b[0]), "r"(b[1]));
}

__device__ __forceinline__ void mma_bf16(float* d, const unsigned* a, const unsigned* b) {
    asm volatile(
        "mma.sync.aligned.m16n8k16.row.col.f32.bf16.bf16.f32 "
        "{%0,%1,%2,%3}, {%4,%5,%6,%7}, {%8,%9}, {%0,%1,%2,%3};\n"
        : "+f"(d[0]), "+f"(d[1]), "+f"(d[2]), "+f"(d[3])
        : "r"(a[0]), "r"(a[1]), "r"(a[2]), "r"(a[3]), "r"(b[0]), "r"(b[1]));
}

__device__ __forceinline__ uint32_t pack2(__nv_bfloat16 a, __nv_bfloat16 b) {
    __nv_bfloat162 v = __halves2bfloat162(a, b);
    return *reinterpret_cast<uint32_t*>(&v);
}

__device__ __forceinline__ void split_bf16(float v, __nv_bfloat16& h, __nv_bfloat16& l) {
    h = __float2bfloat16_rn(v);
    l = __float2bfloat16_rn(v - __bfloat162float(h));
}

__device__ __forceinline__ void cp16(uint32_t saddr, const void* gaddr) {
    asm volatile("cp.async.cg.shared.global [%0], [%1], 16;"
                 :: "r"(saddr), "l"(gaddr) : "memory");
}
#define CP_COMMIT() asm volatile("cp.async.commit_group;" ::: "memory")
#define CP_WAIT1()  asm volatile("cp.async.wait_group 1;" ::: "memory")
#define CP_WAIT0()  asm volatile("cp.async.wait_group 0;" ::: "memory")

// ---------------------------------------------------------------------------
// Zero the rowsum accumulator (kernel-launch-only graph; no memset nodes).
// ---------------------------------------------------------------------------
__global__ void zero_rowsum_kernel(float* __restrict__ rs) {
    rs[blockIdx.x * 256 + threadIdx.x] = 0.0f;
}

// ---------------------------------------------------------------------------
// fp32 projection (Q and K only; tiny: Cq=64)
// out[b][n][o] = sum_c W[o][c] * x[b][c][n] + bias[o]
// ---------------------------------------------------------------------------
__global__ void proj_kernel(const float* __restrict__ x,
                            const float* __restrict__ W,
                            const float* __restrict__ bias,
                            float* __restrict__ out, int Co) {
    const int n0 = blockIdx.x * 128;
    const int o0 = blockIdx.y * 64;
    const int b  = blockIdx.z;
    __shared__ float xs[32][128];
    __shared__ float ws[64][33];
    const int t  = threadIdx.x;
    const int ox = t & 15;
    const int ny = t >> 4;
    float acc[8][4] = {};
    const float* xb = x + (size_t)b * Cch * Np;

    for (int c0 = 0; c0 < Cch; c0 += 32) {
        #pragma unroll
        for (int r = 0; r < 16; r++) {
            int l = t + 256 * r;
            int cc = l >> 7, nn = l & 127;
            xs[cc][nn] = xb[(size_t)(c0 + cc) * Np + n0 + nn];
        }
        #pragma unroll
        for (int r = 0; r < 8; r++) {
            int l = t + 256 * r;
            int oo = l >> 5, cc = l & 31;
            ws[oo][cc] = W[(o0 + oo) * Cch + c0 + cc];
        }
        __syncthreads();
        #pragma unroll
        for (int cc = 0; cc < 32; cc++) {
            float a[8], bb[4];
            #pragma unroll
            for (int i = 0; i < 8; i++) a[i] = xs[cc][ny + 16 * i];
            #pragma unroll
            for (int j = 0; j < 4; j++) bb[j] = ws[ox + 16 * j][cc];
            #pragma unroll
            for (int i = 0; i < 8; i++)
                #pragma unroll
                for (int j = 0; j < 4; j++) acc[i][j] += a[i] * bb[j];
        }
        __syncthreads();
    }
    #pragma unroll
    for (int j = 0; j < 4; j++) {
        float bv = bias[o0 + ox + 16 * j];
        #pragma unroll
        for (int i = 0; i < 8; i++) {
            int n = n0 + ny + 16 * i;
            out[((size_t)b * Np + n) * Co + o0 + ox + 16 * j] = acc[i][j] + bv;
        }
    }
}

// ---------------------------------------------------------------------------
// V projection via tf32 MMA. Emits V^T bf16: vt[b][c][m].
//   v[c][m] = sum_k Wv[c][k] * x[b][k][m] + bv[c]
// ---------------------------------------------------------------------------
#define WS_STRIDE 36
#define XS_STRIDE 136
#define WS_BUF (128 * WS_STRIDE)
#define XS_BUF (32 * XS_STRIDE)
#define VP_SMEM ((2 * WS_BUF + 2 * XS_BUF) * 4)   // 71680 bytes

__global__ __launch_bounds__(256) void vproj_tc_kernel(
        const float* __restrict__ x,
        const float* __restrict__ W,
        const float* __restrict__ bias,
        __nv_bfloat16* __restrict__ vt) {
    const int nB = blockIdx.x * 128;
    const int cB = blockIdx.y * 128;
    const int b  = blockIdx.z;

    extern __shared__ unsigned sm[];
    unsigned* Ws = sm;
    unsigned* Xs = sm + 2 * WS_BUF;

    const int t    = threadIdx.x;
    const int wid  = t >> 5;
    const int lane = t & 31;
    const int gid  = lane >> 2;
    const int tig  = lane & 3;
    const int wc   = (wid >> 2) * 64;
    const int wn   = (wid & 3) * 32;

    const float* xb = x + (size_t)b * Cch * Np;

    float acc[4][4][4] = {};
    float4 wst[4], xst[4];

    #pragma unroll
    for (int r = 0; r < 4; r++) {
        int l4 = t + 256 * r;
        wst[r] = *(const float4*)(W + (size_t)(cB + (l4 >> 3)) * Cch + (l4 & 7) * 4);
        xst[r] = *(const float4*)(xb + (size_t)(l4 >> 5) * Np + nB + (l4 & 31) * 4);
    }
    #pragma unroll
    for (int r = 0; r < 4; r++) {
        int l4 = t + 256 * r;
        unsigned* wd = Ws + (l4 >> 3) * WS_STRIDE + (l4 & 7) * 4;
        wd[0] = f2tf32(wst[r].x); wd[1] = f2tf32(wst[r].y);
        wd[2] = f2tf32(wst[r].z); wd[3] = f2tf32(wst[r].w);
        unsigned* xd = Xs + (l4 >> 5) * XS_STRIDE + (l4 & 31) * 4;
        xd[0] = f2tf32(xst[r].x); xd[1] = f2tf32(xst[r].y);
        xd[2] = f2tf32(xst[r].z); xd[3] = f2tf32(xst[r].w);
    }
    __syncthreads();

    const int NI = Cch / 32;
    for (int it = 0; it < NI; it++) {
        const int cur = it & 1;
        if (it + 1 < NI) {
            const int c0 = (it + 1) * 32;
            #pragma unroll
            for (int r = 0; r < 4; r++) {
                int l4 = t + 256 * r;
                wst[r] = *(const float4*)(W + (size_t)(cB + (l4 >> 3)) * Cch + c0 + (l4 & 7) * 4);
                xst[r] = *(const float4*)(xb + (size_t)(c0 + (l4 >> 5)) * Np + nB + (l4 & 31) * 4);
            }
        }
        const unsigned* Wc = Ws + cur * WS_BUF;
        const unsigned* Xc = Xs + cur * XS_BUF;
        #pragma unroll
        for (int ks = 0; ks < 4; ks++) {
            const int kb = ks * 8;
            unsigned afr[4][4];
            #pragma unroll
            for (int mt = 0; mt < 4; mt++) {
                int row = wc + mt * 16 + gid;
                afr[mt][0] = Wc[row * WS_STRIDE + kb + tig];
                afr[mt][1] = Wc[(row + 8) * WS_STRIDE + kb + tig];
                afr[mt][2] = Wc[row * WS_STRIDE + kb + tig + 4];
                afr[mt][3] = Wc[(row + 8) * WS_STRIDE + kb + tig + 4];
            }
            unsigned bfr[4][2];
            #pragma unroll
            for (int nt = 0; nt < 4; nt++) {
                int col = wn + nt * 8 + gid;
                bfr[nt][0] = Xc[(kb + tig) * XS_STRIDE + col];
                bfr[nt][1] = Xc[(kb + tig + 4) * XS_STRIDE + col];
            }
            #pragma unroll
            for (int mt = 0; mt < 4; mt++)
                #pragma unroll
                for (int nt = 0; nt < 4; nt++)
                    mma_tf32(acc[mt][nt], afr[mt], bfr[nt]);
        }
        if (it + 1 < NI) {
            unsigned* Wd = Ws + (cur ^ 1) * WS_BUF;
            unsigned* Xd = Xs + (cur ^ 1) * XS_BUF;
            #pragma unroll
            for (int r = 0; r < 4; r++) {
                int l4 = t + 256 * r;
                unsigned* wd = Wd + (l4 >> 3) * WS_STRIDE + (l4 & 7) * 4;
                wd[0] = f2tf32(wst[r].x); wd[1] = f2tf32(wst[r].y);
                wd[2] = f2tf32(wst[r].z); wd[3] = f2tf32(wst[r].w);
                unsigned* xd = Xd + (l4 >> 5) * XS_STRIDE + (l4 & 31) * 4;
                xd[0] = f2tf32(xst[r].x); xd[1] = f2tf32(xst[r].y);
                xd[2] = f2tf32(xst[r].z); xd[3] = f2tf32(xst[r].w);
            }
            __syncthreads();
        }
    }

    // Epilogue: round to bf16, store V^T [c][m=n]
    __nv_bfloat16* Vb = vt + (size_t)b * Cch * Np;
    #pragma unroll
    for (int mt = 0; mt < 4; mt++) {
        int c = cB + wc + mt * 16 + gid;
        float b0 = bias[c], b1 = bias[c + 8];
        #pragma unroll
        for (int nt = 0; nt < 4; nt++) {
            int n = nB + wn + nt * 8 + 2 * tig;
            *(uint32_t*)(Vb + (size_t)c * Np + n) =
                pack2(__float2bfloat16_rn(acc[mt][nt][0] + b0),
                      __float2bfloat16_rn(acc[mt][nt][1] + b0));
            *(uint32_t*)(Vb + (size_t)(c + 8) * Np + n) =
                pack2(__float2bfloat16_rn(acc[mt][nt][2] + b1),
                      __float2bfloat16_rn(acc[mt][nt][3] + b1));
        }
    }
}

// ---------------------------------------------------------------------------
// sim via 3x bf16 split MMA (hh + hl + lh), FUSED exp epilogue:
//   e[n][m] = exp(q.k - EXP_OFF)  -> bf16 P;  rowsum[n] += partial sums.
// ---------------------------------------------------------------------------
#define QB_STRIDE 20
#define QB_BUF (128 * QB_STRIDE)     // 2560 words = 10240 B per plane

__global__ __launch_bounds__(256) void sim_bf16_kernel(
        const float* __restrict__ q,
        const float* __restrict__ k,
        __nv_bfloat16* __restrict__ P,
        float* __restrict__ rowsum) {
    const int m0 = blockIdx.x * 128;
    const int n0 = blockIdx.y * 128;
    const int b  = blockIdx.z;

    __shared__ uint32_t qh[QB_BUF], ql[QB_BUF], kh[QB_BUF], kl[QB_BUF];

    const int t    = threadIdx.x;
    const int wid  = t >> 5;
    const int lane = t & 31;
    const int gid  = lane >> 2;
    const int tig  = lane & 3;
    const int wn   = (wid >> 2) * 64;
    const int wm   = (wid & 3) * 32;

    const float* qb = q + ((size_t)b * Np + n0) * Cqd;
    const float* kb = k + ((size_t)b * Np + m0) * Cqd;

    float acc[4][4][4] = {};

    for (int c0 = 0; c0 < Cqd; c0 += 32) {
        if (c0) __syncthreads();
        #pragma unroll
        for (int r = 0; r < 4; r++) {
            int l4 = t + 256 * r;
            int row = l4 >> 3, j4 = (l4 & 7) * 4;
            float4 vq = *(const float4*)(qb + row * Cqd + c0 + j4);
            float4 vk = *(const float4*)(kb + row * Cqd + c0 + j4);
            __nv_bfloat16 hx, lx, hy, ly, hz, lz, hw, lw;
            int w0 = row * QB_STRIDE + (j4 >> 1);
            split_bf16(vq.x, hx, lx); split_bf16(vq.y, hy, ly);
            split_bf16(vq.z, hz, lz); split_bf16(vq.w, hw, lw);
            qh[w0]     = pack2(hx, hy); qh[w0 + 1] = pack2(hz, hw);
            ql[w0]     = pack2(lx, ly); ql[w0 + 1] = pack2(lz, lw);
            split_bf16(vk.x, hx, lx); split_bf16(vk.y, hy, ly);
            split_bf16(vk.z, hz, lz); split_bf16(vk.w, hw, lw);
            kh[w0]     = pack2(hx, hy); kh[w0 + 1] = pack2(hz, hw);
            kl[w0]     = pack2(lx, ly); kl[w0 + 1] = pack2(lz, lw);
        }
        __syncthreads();

        #pragma unroll
        for (int ks = 0; ks < 2; ks++) {
            const int kb8 = ks * 8;
            unsigned ah[4][4], al[4][4];
            #pragma unroll
            for (int mt = 0; mt < 4; mt++) {
                int row = wn + mt * 16 + gid;
                ah[mt][0] = qh[row * QB_STRIDE + kb8 + tig];
                ah[mt][1] = qh[(row + 8) * QB_STRIDE + kb8 + tig];
                ah[mt][2] = qh[row * QB_STRIDE + kb8 + tig + 4];
                ah[mt][3] = qh[(row + 8) * QB_STRIDE + kb8 + tig + 4];
                al[mt][0] = ql[row * QB_STRIDE + kb8 + tig];
                al[mt][1] = ql[(row + 8) * QB_STRIDE + kb8 + tig];
                al[mt][2] = ql[row * QB_STRIDE + kb8 + tig + 4];
                al[mt][3] = ql[(row + 8) * QB_STRIDE + kb8 + tig + 4];
            }
            unsigned bh[4][2], bl[4][2];
            #pragma unroll
            for (int nt = 0; nt < 4; nt++) {
                int col = wm + nt * 8 + gid;
                bh[nt][0] = kh[col * QB_STRIDE + kb8 + tig];
                bh[nt][1] = kh[col * QB_STRIDE + kb8 + tig + 4];
                bl[nt][0] = kl[col * QB_STRIDE + kb8 + tig];
                bl[nt][1] = kl[col * QB_STRIDE + kb8 + tig + 4];
            }
            #pragma unroll
            for (int mt = 0; mt < 4; mt++)
                #pragma unroll
                for (int nt = 0; nt < 4; nt++) {
                    mma_bf16(acc[mt][nt], ah[mt], bl[nt]);
                    mma_bf16(acc[mt][nt], al[mt], bh[nt]);
                    mma_bf16(acc[mt][nt], ah[mt], bh[nt]);
                }
        }
    }

    // Fused exp epilogue
    #pragma unroll
    for (int mt = 0; mt < 4; mt++)
        #pragma unroll
        for (int nt = 0; nt < 4; nt++)
            #pragma unroll
            for (int v = 0; v < 4; v++)
                acc[mt][nt][v] = __expf(acc[mt][nt][v] - EXP_OFF);

    __nv_bfloat16* Pb = P + ((size_t)b * Np + n0) * Np + m0;
    #pragma unroll
    for (int mt = 0; mt < 4; mt++) {
        int n = wn + mt * 16 + gid;
        #pragma unroll
        for (int nt = 0; nt < 4; nt++) {
            int m = wm + nt * 8 + 2 * tig;
            *(uint32_t*)(Pb + (size_t)n * Np + m) =
                pack2(__float2bfloat16_rn(acc[mt][nt][0]),
                      __float2bfloat16_rn(acc[mt][nt][1]));
            *(uint32_t*)(Pb + (size_t)(n + 8) * Np + m) =
                pack2(__float2bfloat16_rn(acc[mt][nt][2]),
                      __float2bfloat16_rn(acc[mt][nt][3]));
        }
    }

    float* rs = rowsum + (size_t)b * Np + n0;
    #pragma unroll
    for (int mt = 0; mt < 4; mt++) {
        float s0 = 0.f, s1 = 0.f;
        #pragma unroll
        for (int nt = 0; nt < 4; nt++) {
            s0 += acc[mt][nt][0] + acc[mt][nt][1];
            s1 += acc[mt][nt][2] + acc[mt][nt][3];
        }
        s0 += __shfl_xor_sync(0xFFFFFFFF, s0, 1);
        s0 += __shfl_xor_sync(0xFFFFFFFF, s0, 2);
        s1 += __shfl_xor_sync(0xFFFFFFFF, s1, 1);
        s1 += __shfl_xor_sync(0xFFFFFFFF, s1, 2);
        if (tig == 0) {
            int n = wn + mt * 16 + gid;
            atomicAdd(rs + n, s0);
            atomicAdd(rs + n + 8, s1);
        }
    }
}

// ---------------------------------------------------------------------------
// ctx via bf16 mma.sync m16n8k16, 128x128 tile, cp.async 3-stage pipeline:
// iter it: wait_group(1) [chunk it resident] -> sync -> issue chunk it+2
// into buf (it+2)%3 -> compute buf it%3. Two full iterations of load slack.
// Buffer-reuse safety: issue targets the buffer computed at it-1; the sync
// after wait orders all warps past that compute.
//   out[b][c][n] = g * (sum_m e[n][m]*V[m][c]) / rowsum[n] + x
// Dynamic smem: 3 * (2560 + 2560) * 4 = 61440 bytes (opt-in attr).
// ---------------------------------------------------------------------------
#define PS2 20
#define CT_BUF (128 * PS2)                      // 2560 words per operand buffer
#define CTX3_SMEM (6 * CT_BUF * 4)              // 61440 bytes

__global__ __launch_bounds__(256) void ctx_bf16_kernel(
        const __nv_bfloat16* __restrict__ P,
        const __nv_bfloat16* __restrict__ Vt,
        const float* __restrict__ rowsum,
        const float* __restrict__ x,
        const float* __restrict__ gamma,
        float* __restrict__ out) {
    const int n0 = blockIdx.x * 128;
    const int c0 = blockIdx.y * 128;
    const int b  = blockIdx.z;

    extern __shared__ uint32_t smctx[];
    uint32_t* Ps = smctx;               // [3][CT_BUF]
    uint32_t* Vs = smctx + 3 * CT_BUF;  // [3][CT_BUF]

    const int t    = threadIdx.x;
    const int wid  = t >> 5;
    const int lane = t & 31;
    const int gid  = lane >> 2;
    const int tig  = lane & 3;
    const int wn   = (wid >> 2) * 64;
    const int wc   = (wid & 3) * 32;

    const __nv_bfloat16* Pb = P + ((size_t)b * Np + n0) * Np;
    const __nv_bfloat16* Vb = Vt + ((size_t)b * Cch + c0) * Np;

    // Per-thread staging coordinates: 512 16B units per operand per chunk,
    // covered as 2 rows x (t>>2 in 0..63), unit su = t&3.
    const int srow = t >> 2;
    const int su   = t & 3;
    const uint32_t ps_base = (uint32_t)__cvta_generic_to_shared(Ps);
    const uint32_t vs_base = (uint32_t)__cvta_generic_to_shared(Vs);

    float acc[4][4][4] = {};

    // Issue one chunk's copies into stage buffer s (4 x 16B per thread).
    auto issue_chunk = [&](int chunk, int s) {
        const __nv_bfloat16* Pn = Pb + chunk * 32;
        const __nv_bfloat16* Vn = Vb + chunk * 32;
        uint32_t pdst = ps_base + (uint32_t)(s * CT_BUF) * 4;
        uint32_t vdst = vs_base + (uint32_t)(s * CT_BUF) * 4;
        #pragma unroll
        for (int r = 0; r < 2; r++) {
            int row = srow + 64 * r;
            uint32_t off = (uint32_t)(row * PS2 + su * 4) * 4;
            cp16(pdst + off, Pn + (size_t)row * Np + su * 8);
            cp16(vdst + off, Vn + (size_t)row * Np + su * 8);
        }
        CP_COMMIT();
    };

    // Prologue: stage chunks 0 and 1.
    issue_chunk(0, 0);
    issue_chunk(1, 1);

    const int NI = Np / 32;  // 128 chunks
    for (int it = 0; it < NI; it++) {
        if (it + 2 < NI) CP_WAIT1(); else CP_WAIT0();
        __syncthreads();
        if (it + 2 < NI) {
            int s = it + 2; s -= (s / 3) * 3;     // (it+2) % 3
            issue_chunk(it + 2, s);
        }
        int cs = it - (it / 3) * 3;               // it % 3
        const uint32_t* Pc = Ps + cs * CT_BUF;
        const uint32_t* Vc = Vs + cs * CT_BUF;
        #pragma unroll
        for (int ks = 0; ks < 2; ks++) {
            const int kb = ks * 8;
            unsigned afr[4][4];
            #pragma unroll
            for (int mt = 0; mt < 4; mt++) {
                int row = wn + mt * 16 + gid;
                afr[mt][0] = Pc[row * PS2 + kb + tig];
                afr[mt][1] = Pc[(row + 8) * PS2 + kb + tig];
                afr[mt][2] = Pc[row * PS2 + kb + tig + 4];
                afr[mt][3] = Pc[(row + 8) * PS2 + kb + tig + 4];
            }
            unsigned bfr[4][2];
            #pragma unroll
            for (int nt = 0; nt < 4; nt++) {
                int col = wc + nt * 8 + gid;
                bfr[nt][0] = Vc[col * PS2 + kb + tig];
                bfr[nt][1] = Vc[col * PS2 + kb + tig + 4];
            }
            #pragma unroll
            for (int mt = 0; mt < 4; mt++)
                #pragma unroll
                for (int nt = 0; nt < 4; nt++)
                    mma_bf16(acc[mt][nt], afr[mt], bfr[nt]);
        }
    }

    // Epilogue: out[b][c][n] = g * acc / rowsum[n] + x
    const float g = gamma[0];
    const float* rs = rowsum + (size_t)b * Np + n0;
    #pragma unroll
    for (int mt = 0; mt < 4; mt++) {
        int n = n0 + wn + mt * 16 + gid;
        float inv0 = g / rs[wn + mt * 16 + gid];
        float inv1 = g / rs[wn + mt * 16 + gid + 8];
        #pragma unroll
        for (int nt = 0; nt < 4; nt++) {
            int c = c0 + wc + nt * 8 + 2 * tig;
            size_t i00 = ((size_t)b * Cch + c) * Np + n;
            size_t i01 = ((size_t)b * Cch + c + 1) * Np + n;
            out[i00]     = inv0 * acc[mt][nt][0] + x[i00];
            out[i01]     = inv0 * acc[mt][nt][1] + x[i01];
            out[i00 + 8] = inv1 * acc[mt][nt][2] + x[i00 + 8];
            out[i01 + 8] = inv1 * acc[mt][nt][3] + x[i01 + 8];
        }
    }
}

// ---------------------------------------------------------------------------
extern "C" void kernel_launch(void* const* d_in, const int* in_sizes, int n_in,
                              void* d_out, int out_size) {
    const float* x     = (const float*)d_in[0];
    const float* Wq    = (const float*)d_in[1];
    const float* bq    = (const float*)d_in[2];
    const float* Wk    = (const float*)d_in[3];
    const float* bk    = (const float*)d_in[4];
    const float* Wv    = (const float*)d_in[5];
    const float* bv    = (const float*)d_in[6];
    const float* gamma = (const float*)d_in[7];
    float* out = (float*)d_out;

    float *q, *k, *rsum;
    __nv_bfloat16 *pb, *vt;
    cudaGetSymbolAddress((void**)&q, g_q);
    cudaGetSymbolAddress((void**)&k, g_k);
    cudaGetSymbolAddress((void**)&rsum, g_rowsum);
    cudaGetSymbolAddress((void**)&pb, g_pb);
    cudaGetSymbolAddress((void**)&vt, g_vt);

    static int smem_set = 0;
    if (!smem_set) {
        cudaFuncSetAttribute(vproj_tc_kernel,
                             cudaFuncAttributeMaxDynamicSharedMemorySize, VP_SMEM);
        cudaFuncSetAttribute(ctx_bf16_kernel,
                             cudaFuncAttributeMaxDynamicSharedMemorySize, CTX3_SMEM);
        smem_set = 1;
    }

    dim3 thr(256);
    zero_rowsum_kernel<<<Bsz * Np / 256, thr>>>(rsum);
    proj_kernel<<<dim3(Np / 128, 1, Bsz), thr>>>(x, Wq, bq, q, Cqd);
    proj_kernel<<<dim3(Np / 128, 1, Bsz), thr>>>(x, Wk, bk, k, Cqd);
    vproj_tc_kernel<<<dim3(Np / 128, Cch / 128, Bsz), thr, VP_SMEM>>>(x, Wv, bv, vt);
    sim_bf16_kernel<<<dim3(Np / 128, Np / 128, Bsz), thr>>>(q, k, pb, rsum);
    ctx_bf16_kernel<<<dim3(Np / 128, Cch / 128, Bsz), thr, CTX3_SMEM>>>(pb, vt, rsum, x, gamma, out);
}